// round 10
// baseline (speedup 1.0000x reference)
#include <cuda_runtime.h>
#include <math.h>

#define L    128
#define NB   64
#define DD   768
#define IN   64
#define OUTD 64
#define NO   32
#define EPSV 1e-8f
#define NCH  16         // l-chunks
#define LCH  8          // l per chunk
#define TILE 2080       // 32 * 65 floats per staged l-tile

// ---------------- scratch (device globals) -----------------------------------
__device__ float g_mu_in[L * NB * IN];                 // (l, n, i)
__device__ float g_fa[L * NB];                         // (l, n)
__device__ float g_V [(size_t)L * NO * NB * OUTD];     // (l, o, n, j)  64 MB
__device__ float g_mut[NB * OUTD * NO];                // (n, j, o)
__device__ float g_ivt[NB * OUTD * NO];                // (n, j, o) : 1/(2var+eps)
__device__ float g_a[NB * NO];                         // (n, o) activation logit
__device__ float g_lvp[NB * 4 * NO];                   // (n, jg, o) partial sum log var
__device__ float g_q1[NB * NCH * OUTD * NO];           // chunk partials 8 MB
__device__ float g_q2[NB * NCH * OUTD * NO];           // 8 MB
__device__ float g_q0[NB * NCH * NO];
__device__ float g_qbu[NB * NCH * NO];
__device__ float g_qfa[NB * NCH];

// ---------------- packed f32x2 helpers ---------------------------------------
__device__ __forceinline__ unsigned long long pk(float x, float y) {
    unsigned long long r; asm("mov.b64 %0, {%1, %2};" : "=l"(r) : "f"(x), "f"(y)); return r;
}
__device__ __forceinline__ void fma2(unsigned long long& d, unsigned long long a, unsigned long long b) {
    asm("fma.rn.f32x2 %0, %1, %2, %0;" : "+l"(d) : "l"(a), "l"(b));
}
__device__ __forceinline__ float2 upk(unsigned long long v) {
    float2 r; asm("mov.b64 {%0, %1}, %2;" : "=f"(r.x), "=f"(r.y) : "l"(v)); return r;
}

// ---------------- kernel 1: a_in + mu_in (n-split 2, fused score) -------------
__global__ __launch_bounds__(256) void front_kernel(
    const float* __restrict__ x,      // (N, L, D)
    const float* __restrict__ Wsc,    // (L, D)
    const float* __restrict__ Bsc,    // (L)
    const float* __restrict__ Wc,     // (L, D, IN)
    const float* __restrict__ Bc)     // (L, IN)
{
    __shared__ __align__(8) float As[32][34];      // [k][n-half]
    __shared__ __align__(16) float Bs[32][64];     // [k][i]
    __shared__ float s_ws[32];
    __shared__ float s_sc[8][32];

    const int bid = blockIdx.x;
    const int l   = bid >> 1;
    const int n0  = (bid & 1) * 32;
    const int tid = threadIdx.x;
    const int tn  = tid >> 4;
    const int tj  = tid & 15;

    const int sq = tid >> 5, sn = tid & 31;
    float sc = 0.f;

    unsigned long long acc[4] = {};

    for (int kk = 0; kk < DD; kk += 32) {
        #pragma unroll
        for (int p = 0; p < 4; p++) {
            int e = tid + p * 256;
            int n = e >> 5, k = e & 31;
            As[k][n] = __ldcs(&x[((size_t)(n0 + n) * L + l) * DD + kk + k]);
        }
        #pragma unroll
        for (int p = 0; p < 8; p++) {
            int e = tid + p * 256;
            int k = e >> 6, i = e & 63;
            Bs[k][i] = __ldcs(&Wc[(size_t)l * DD * IN + (size_t)(kk + k) * IN + i]);
        }
        if (tid < 32) s_ws[tid] = Wsc[(size_t)l * DD + kk + tid];
        __syncthreads();

        #pragma unroll
        for (int k = 0; k < 32; k++) {
            float2 a0 = reinterpret_cast<const float2*>(&As[k][0])[tn];
            unsigned long long A0;
            asm("mov.b64 %0, {%1, %2};" : "=l"(A0) : "f"(a0.x), "f"(a0.y));
            float4 b = reinterpret_cast<const float4*>(&Bs[k][0])[tj];
            unsigned long long B0 = pk(b.x, b.x), B1 = pk(b.y, b.y),
                               B2 = pk(b.z, b.z), B3 = pk(b.w, b.w);
            fma2(acc[0], A0, B0); fma2(acc[1], A0, B1);
            fma2(acc[2], A0, B2); fma2(acc[3], A0, B3);
        }

        #pragma unroll
        for (int k4 = 0; k4 < 4; k4++)
            sc = fmaf(As[sq * 4 + k4][sn], s_ws[sq * 4 + k4], sc);
        __syncthreads();
    }

    #pragma unroll
    for (int c = 0; c < 4; c++) {
        int i = tj * 4 + c;
        float2 v2 = upk(acc[c]);
        float bb = Bc[l * IN + i];
        int n = n0 + tn * 2;
        float v0 = v2.x + bb, v1 = v2.y + bb;
        g_mu_in[(size_t)l * NB * IN + (size_t)n * IN + i]       = v0 * normcdff(v0);
        g_mu_in[(size_t)l * NB * IN + (size_t)(n + 1) * IN + i] = v1 * normcdff(v1);
    }

    s_sc[sq][sn] = sc;
    __syncthreads();
    if (tid < 32) {
        float s = Bsc[l];
        #pragma unroll
        for (int q = 0; q < 8; q++) s += s_sc[q][tid];
        g_fa[l * NB + n0 + tid] = 1.f / (1.f + expf(-s));
    }
}

// ---------------- kernel 2: votes V (packed FMA) ------------------------------
__global__ __launch_bounds__(256) void vote_kernel(
    const float* __restrict__ Wv,    // (L, NO, IN, OUT)
    const float* __restrict__ Bv)    // (L, NO, OUT)
{
    __shared__ __align__(8) float As[64][66];      // [i][n]
    __shared__ __align__(16) float Bs[64][64];     // [i][j]

    const int lo  = blockIdx.x;   // l*32 + o
    const int l   = lo >> 5;
    const int tid = threadIdx.x;

    const float* A = g_mu_in + (size_t)l * NB * IN;
    const float* B = Wv + (size_t)lo * IN * OUTD;

    #pragma unroll
    for (int p = 0; p < 16; p++) {
        int e = tid + p * 256;
        int n = e >> 6, i = e & 63;
        As[i][n] = A[e];
        Bs[e >> 6][e & 63] = __ldcs(&B[e]);
    }
    __syncthreads();

    const int tn = tid >> 4, tj = tid & 15;
    unsigned long long acc[2][4];
    #pragma unroll
    for (int p = 0; p < 2; p++)
        #pragma unroll
        for (int c = 0; c < 4; c++) acc[p][c] = 0ULL;

    #pragma unroll
    for (int i = 0; i < 64; i++) {
        const float2* ar = reinterpret_cast<const float2*>(&As[i][0]);
        float2 a0 = ar[tn * 2];
        float2 a1 = ar[tn * 2 + 1];
        unsigned long long A0, A1;
        asm("mov.b64 %0, {%1, %2};" : "=l"(A0) : "f"(a0.x), "f"(a0.y));
        asm("mov.b64 %0, {%1, %2};" : "=l"(A1) : "f"(a1.x), "f"(a1.y));
        float4 b = reinterpret_cast<const float4*>(&Bs[i][0])[tj];
        unsigned long long B0 = pk(b.x, b.x), B1 = pk(b.y, b.y),
                           B2 = pk(b.z, b.z), B3 = pk(b.w, b.w);
        fma2(acc[0][0], A0, B0); fma2(acc[0][1], A0, B1);
        fma2(acc[0][2], A0, B2); fma2(acc[0][3], A0, B3);
        fma2(acc[1][0], A1, B0); fma2(acc[1][1], A1, B1);
        fma2(acc[1][2], A1, B2); fma2(acc[1][3], A1, B3);
    }

    float4 bias;
    bias.x = __ldcs(&Bv[(size_t)lo * OUTD + tj * 4 + 0]);
    bias.y = __ldcs(&Bv[(size_t)lo * OUTD + tj * 4 + 1]);
    bias.z = __ldcs(&Bv[(size_t)lo * OUTD + tj * 4 + 2]);
    bias.w = __ldcs(&Bv[(size_t)lo * OUTD + tj * 4 + 3]);
    float* Vout = g_V + (size_t)lo * NB * OUTD;
    #pragma unroll
    for (int p = 0; p < 2; p++) {
        float2 vx = upk(acc[p][0]), vy = upk(acc[p][1]),
               vz = upk(acc[p][2]), vw = upk(acc[p][3]);
        int n0 = tn * 4 + 2 * p;
        float4 o0 = make_float4(vx.x + bias.x, vy.x + bias.y, vz.x + bias.z, vw.x + bias.w);
        float4 o1 = make_float4(vx.y + bias.x, vy.y + bias.y, vz.y + bias.z, vw.y + bias.w);
        reinterpret_cast<float4*>(Vout + (size_t)n0 * OUTD)[tj]       = o0;
        reinterpret_cast<float4*>(Vout + (size_t)(n0 + 1) * OUTD)[tj] = o1;
    }
}

// ---------------- kernel 3: staged route + EM partials ------------------------
// grid = NB*NCH (bid: n = bid>>4, c = bid&15), block = 256 (8 warps).
// Stages 8 V tiles (32o x 64j each) in dynamic smem ONCE; phase 1 computes
// logits+softmax per warp (lane = o, zero barriers); phase 2 accumulates
// moments from smem. uniform=1: E-step 0 (D = fa/32, skip logits).
__global__ __launch_bounds__(256) void re_kernel(const float* __restrict__ bu,
                                                 int uniform)
{
    extern __shared__ float sm_v[];     // LCH tiles of [32][65]
    __shared__ float s_mu[OUTD * NO];   // (j, o)
    __shared__ float s_iv[OUTD * NO];
    __shared__ float s_C[NO];
    __shared__ float s_D[LCH][NO];

    const int bid = blockIdx.x;
    const int n = bid >> 4, c = bid & (NCH - 1);
    const int tid = threadIdx.x;
    const int w = tid >> 5, lane = tid & 31;

    if (!uniform) {
        const float4* ms = reinterpret_cast<const float4*>(g_mut + (size_t)n * OUTD * NO);
        const float4* is = reinterpret_cast<const float4*>(g_ivt + (size_t)n * OUTD * NO);
        float4* md = reinterpret_cast<float4*>(s_mu);
        float4* id = reinterpret_cast<float4*>(s_iv);
        md[tid] = ms[tid]; md[tid + 256] = ms[tid + 256];
        id[tid] = is[tid]; id[tid + 256] = is[tid + 256];
        if (tid < NO) {
            float a = g_a[n * NO + tid];
            float slv = g_lvp[(n * 4 + 0) * NO + tid] + g_lvp[(n * 4 + 1) * NO + tid]
                      + g_lvp[(n * 4 + 2) * NO + tid] + g_lvp[(n * 4 + 3) * NO + tid];
            float lsig = (a > 0.f) ? -log1pf(expf(-a)) : a - log1pf(expf(a));
            s_C[tid] = lsig - 1.f - 0.5f * 3.14159265358979323846f - 0.5f * slv;
        }
    }

    // stage all 8 l tiles: coalesced LDG.128, transposed-access smem layout
    #pragma unroll
    for (int li = 0; li < LCH; li++) {
        const int l = c * LCH + li;
        #pragma unroll
        for (int r = 0; r < 2; r++) {
            int idx = tid + r * 256;       // 0..511
            int oo = idx >> 4, f4 = idx & 15;
            float4 v = *reinterpret_cast<const float4*>(
                g_V + (((size_t)l * NO + oo) * NB + n) * OUTD + f4 * 4);
            float* d = sm_v + li * TILE + oo * 65 + f4 * 4;
            d[0] = v.x; d[1] = v.y; d[2] = v.z; d[3] = v.w;
        }
    }
    __syncthreads();

    // phase 1: warp w -> l = c*8 + w; lane = o; zero barriers
    const int l = c * LCH + w;
    const float fa = g_fa[l * NB + n];
    float D;
    if (uniform) {
        D = fa * (1.f / 32.f);
    } else {
        const float* vb = sm_v + w * TILE + lane * 65;
        float t = 0.f;
        #pragma unroll
        for (int j = 0; j < OUTD; j++) {
            float v = vb[j];
            float d = v - s_mu[j * NO + lane];
            t = fmaf(d * d, s_iv[j * NO + lane], t);
        }
        float lg = s_C[lane] - t;
        float mx = lg;
        #pragma unroll
        for (int off = 16; off; off >>= 1) mx = fmaxf(mx, __shfl_xor_sync(0xffffffffu, mx, off));
        float e = expf(lg - mx);
        float ss = e;
        #pragma unroll
        for (int off = 16; off; off >>= 1) ss += __shfl_xor_sync(0xffffffffu, ss, off);
        D = fa * (e / ss);
    }
    s_D[w][lane] = D;
    __syncthreads();

    // phase 2: warp w owns j-slice [w*8, w*8+8); lane = o; accumulate over 8 l
    float s1[8] = {}, s2[8] = {};
    const int j0 = w * 8;
    #pragma unroll
    for (int li = 0; li < LCH; li++) {
        float Dl = s_D[li][lane];
        const float* vb = sm_v + li * TILE + lane * 65 + j0;
        #pragma unroll
        for (int jj = 0; jj < 8; jj++) {
            float v = vb[jj];
            float dv = Dl * v;
            s1[jj] += dv;
            s2[jj] = fmaf(dv, v, s2[jj]);
        }
    }
    float* q1 = g_q1 + ((size_t)bid * OUTD + j0) * NO + lane;
    float* q2 = g_q2 + ((size_t)bid * OUTD + j0) * NO + lane;
    #pragma unroll
    for (int jj = 0; jj < 8; jj++) { q1[jj * NO] = s1[jj]; q2[jj * NO] = s2[jj]; }

    if (w == 0) {
        float s0 = 0.f, sbu = 0.f, sfa = 0.f;
        #pragma unroll
        for (int li = 0; li < LCH; li++) {
            int ll = c * LCH + li;
            float Dl = s_D[li][lane];
            s0 += Dl;
            sbu = fmaf(bu[ll], Dl, sbu);
            sfa += g_fa[ll * NB + n];
        }
        g_q0[bid * NO + lane]  = s0;
        g_qbu[bid * NO + lane] = sbu;
        if (lane == 0) g_qfa[bid] = sfa;
    }
}

// ---------------- kernel 4: finalize EM (parallel, one (j,o) per thread) ------
// grid = NB*4 (bid: n = bid>>2, jg = bid&3), block = 512.
__global__ __launch_bounds__(512) void fin_kernel(
    const float* __restrict__ bi, int write_out, float* __restrict__ out)
{
    const int bid = blockIdx.x;
    const int n = bid >> 2, jg = bid & 3;
    const int tid = threadIdx.x;
    const int jj = tid >> 5, o = tid & 31;
    const int j = jg * 16 + jj;

    float s0 = 0.f, sbu = 0.f, sfa = 0.f;
    #pragma unroll
    for (int c = 0; c < NCH; c++) {
        s0  += g_q0[(n * NCH + c) * NO + o];
        sbu += g_qbu[(n * NCH + c) * NO + o];
        sfa += g_qfa[n * NCH + c];
    }
    float denom = s0 + EPSV;
    float a = sbu - bi[o] * (sfa - s0);

    float s1 = 0.f, s2 = 0.f;
    #pragma unroll
    for (int c = 0; c < NCH; c++) {
        size_t p = (((size_t)(n * NCH + c)) * OUTD + j) * NO + o;
        s1 += g_q1[p];
        s2 += g_q2[p];
    }
    float m   = s1 / denom;
    float var = fmaxf((s2 - 2.f * m * s1 + m * m * s0) / denom, 0.f);
    g_mut[((size_t)n * OUTD + j) * NO + o] = m;
    g_ivt[((size_t)n * OUTD + j) * NO + o] = 1.f / (2.f * var + EPSV);

    if (write_out) {
        out[NB * NO + ((size_t)n * NO + o) * OUTD + j] = m;    // mu_out (N, NO, OUT)
        if (jj == 0 && jg == 0) out[n * NO + o] = a;           // a_out (N, NO)
    } else {
        float lv = logf(var + EPSV);
        __shared__ float s_lv[16][NO];
        s_lv[jj][o] = lv;
        __syncthreads();
        if (jj == 0) {
            float slv = 0.f;
            #pragma unroll
            for (int k = 0; k < 16; k++) slv += s_lv[k][o];
            g_lvp[(n * 4 + jg) * NO + o] = slv;
            if (jg == 0) g_a[n * NO + o] = a;
        }
    }
}

// ---------------- launch --------------------------------------------------------
extern "C" void kernel_launch(void* const* d_in, const int* in_sizes, int n_in,
                              void* d_out, int out_size)
{
    const float* x      = (const float*)d_in[0];
    const float* Wscore = (const float*)d_in[1];
    const float* Bscore = (const float*)d_in[2];
    const float* Wcap   = (const float*)d_in[3];
    const float* Bcap   = (const float*)d_in[4];
    const float* Wvote  = (const float*)d_in[5];
    const float* Bvote  = (const float*)d_in[6];
    const float* bu     = (const float*)d_in[7];
    const float* bi     = (const float*)d_in[8];
    float* out = (float*)d_out;

    const int dyn_smem = LCH * TILE * sizeof(float);   // 66560 B
    cudaFuncSetAttribute(re_kernel, cudaFuncAttributeMaxDynamicSharedMemorySize, dyn_smem);

    front_kernel<<<L * 2, 256>>>(x, Wscore, Bscore, Wcap, Bcap);
    vote_kernel<<<L * NO, 256>>>(Wvote, Bvote);

    // iters = 3: E0(uniform), route+E ×2
    re_kernel<<<NB * NCH, 256, dyn_smem>>>(bu, 1);
    fin_kernel<<<NB * 4, 512>>>(bi, 0, out);
    re_kernel<<<NB * NCH, 256, dyn_smem>>>(bu, 0);
    fin_kernel<<<NB * 4, 512>>>(bi, 0, out);
    re_kernel<<<NB * NCH, 256, dyn_smem>>>(bu, 0);
    fin_kernel<<<NB * 4, 512>>>(bi, 1, out);
}

// round 11
// speedup vs baseline: 1.0357x; 1.0357x over previous
#include <cuda_runtime.h>
#include <math.h>

#define L    128
#define NB   64
#define DD   768
#define IN   64
#define OUTD 64
#define NO   32
#define EPSV 1e-8f
#define NCH  16         // l-chunks
#define LCH  8          // l per chunk

// ---------------- scratch (device globals) -----------------------------------
__device__ float g_mu_in[L * NB * IN];                 // (l, n, i)
__device__ float g_fa[L * NB];                         // (l, n)
__device__ float g_V [(size_t)L * NO * NB * OUTD];     // (l, o, n, j)  64 MB
__device__ float g_mut[NB * NO * OUTD];                // (n, o, j)
__device__ float g_ivt[NB * NO * OUTD];                // (n, o, j) : 1/(2var+eps)
__device__ float g_C[NB * NO];                         // (n, o) routing constant
__device__ float g_q1[NB * NCH * NO * OUTD];           // chunk partials (bid, o, j)
__device__ float g_q2[NB * NCH * NO * OUTD];
__device__ float g_q0[NB * NCH * NO];
__device__ float g_qbu[NB * NCH * NO];
__device__ float g_qfa[NB * NCH];

// ---------------- packed f32x2 helpers ---------------------------------------
__device__ __forceinline__ unsigned long long pk(float x, float y) {
    unsigned long long r; asm("mov.b64 %0, {%1, %2};" : "=l"(r) : "f"(x), "f"(y)); return r;
}
__device__ __forceinline__ void fma2(unsigned long long& d, unsigned long long a, unsigned long long b) {
    asm("fma.rn.f32x2 %0, %1, %2, %0;" : "+l"(d) : "l"(a), "l"(b));
}
__device__ __forceinline__ float2 upk(unsigned long long v) {
    float2 r; asm("mov.b64 {%0, %1}, %2;" : "=f"(r.x), "=f"(r.y) : "l"(v)); return r;
}

// ---------------- kernel 1: a_in + mu_in (n-split 2, fused score) -------------
__global__ __launch_bounds__(256) void front_kernel(
    const float* __restrict__ x,      // (N, L, D)
    const float* __restrict__ Wsc,    // (L, D)
    const float* __restrict__ Bsc,    // (L)
    const float* __restrict__ Wc,     // (L, D, IN)
    const float* __restrict__ Bc)     // (L, IN)
{
    __shared__ __align__(8) float As[32][34];      // [k][n-half]
    __shared__ __align__(16) float Bs[32][64];     // [k][i]
    __shared__ float s_ws[32];
    __shared__ float s_sc[8][32];

    const int bid = blockIdx.x;
    const int l   = bid >> 1;
    const int n0  = (bid & 1) * 32;
    const int tid = threadIdx.x;
    const int tn  = tid >> 4;
    const int tj  = tid & 15;

    const int sq = tid >> 5, sn = tid & 31;
    float sc = 0.f;

    unsigned long long acc[4] = {};

    for (int kk = 0; kk < DD; kk += 32) {
        #pragma unroll
        for (int p = 0; p < 4; p++) {
            int e = tid + p * 256;
            int n = e >> 5, k = e & 31;
            As[k][n] = __ldcs(&x[((size_t)(n0 + n) * L + l) * DD + kk + k]);
        }
        #pragma unroll
        for (int p = 0; p < 8; p++) {
            int e = tid + p * 256;
            int k = e >> 6, i = e & 63;
            Bs[k][i] = __ldcs(&Wc[(size_t)l * DD * IN + (size_t)(kk + k) * IN + i]);
        }
        if (tid < 32) s_ws[tid] = Wsc[(size_t)l * DD + kk + tid];
        __syncthreads();

        #pragma unroll
        for (int k = 0; k < 32; k++) {
            float2 a0 = reinterpret_cast<const float2*>(&As[k][0])[tn];
            unsigned long long A0;
            asm("mov.b64 %0, {%1, %2};" : "=l"(A0) : "f"(a0.x), "f"(a0.y));
            float4 b = reinterpret_cast<const float4*>(&Bs[k][0])[tj];
            unsigned long long B0 = pk(b.x, b.x), B1 = pk(b.y, b.y),
                               B2 = pk(b.z, b.z), B3 = pk(b.w, b.w);
            fma2(acc[0], A0, B0); fma2(acc[1], A0, B1);
            fma2(acc[2], A0, B2); fma2(acc[3], A0, B3);
        }

        #pragma unroll
        for (int k4 = 0; k4 < 4; k4++)
            sc = fmaf(As[sq * 4 + k4][sn], s_ws[sq * 4 + k4], sc);
        __syncthreads();
    }

    #pragma unroll
    for (int c = 0; c < 4; c++) {
        int i = tj * 4 + c;
        float2 v2 = upk(acc[c]);
        float bb = Bc[l * IN + i];
        int n = n0 + tn * 2;
        float v0 = v2.x + bb, v1 = v2.y + bb;
        g_mu_in[(size_t)l * NB * IN + (size_t)n * IN + i]       = v0 * normcdff(v0);
        g_mu_in[(size_t)l * NB * IN + (size_t)(n + 1) * IN + i] = v1 * normcdff(v1);
    }

    s_sc[sq][sn] = sc;
    __syncthreads();
    if (tid < 32) {
        float s = Bsc[l];
        #pragma unroll
        for (int q = 0; q < 8; q++) s += s_sc[q][tid];
        g_fa[l * NB + n0 + tid] = 1.f / (1.f + expf(-s));
    }
}

// ---------------- kernel 2: votes V (packed FMA) ------------------------------
__global__ __launch_bounds__(256) void vote_kernel(
    const float* __restrict__ Wv,    // (L, NO, IN, OUT)
    const float* __restrict__ Bv)    // (L, NO, OUT)
{
    __shared__ __align__(8) float As[64][66];      // [i][n]
    __shared__ __align__(16) float Bs[64][64];     // [i][j]

    const int lo  = blockIdx.x;   // l*32 + o
    const int l   = lo >> 5;
    const int tid = threadIdx.x;

    const float* A = g_mu_in + (size_t)l * NB * IN;
    const float* B = Wv + (size_t)lo * IN * OUTD;

    #pragma unroll
    for (int p = 0; p < 16; p++) {
        int e = tid + p * 256;
        int n = e >> 6, i = e & 63;
        As[i][n] = A[e];
        Bs[e >> 6][e & 63] = __ldcs(&B[e]);
    }
    __syncthreads();

    const int tn = tid >> 4, tj = tid & 15;
    unsigned long long acc[2][4];
    #pragma unroll
    for (int p = 0; p < 2; p++)
        #pragma unroll
        for (int c = 0; c < 4; c++) acc[p][c] = 0ULL;

    #pragma unroll
    for (int i = 0; i < 64; i++) {
        const float2* ar = reinterpret_cast<const float2*>(&As[i][0]);
        float2 a0 = ar[tn * 2];
        float2 a1 = ar[tn * 2 + 1];
        unsigned long long A0, A1;
        asm("mov.b64 %0, {%1, %2};" : "=l"(A0) : "f"(a0.x), "f"(a0.y));
        asm("mov.b64 %0, {%1, %2};" : "=l"(A1) : "f"(a1.x), "f"(a1.y));
        float4 b = reinterpret_cast<const float4*>(&Bs[i][0])[tj];
        unsigned long long B0 = pk(b.x, b.x), B1 = pk(b.y, b.y),
                           B2 = pk(b.z, b.z), B3 = pk(b.w, b.w);
        fma2(acc[0][0], A0, B0); fma2(acc[0][1], A0, B1);
        fma2(acc[0][2], A0, B2); fma2(acc[0][3], A0, B3);
        fma2(acc[1][0], A1, B0); fma2(acc[1][1], A1, B1);
        fma2(acc[1][2], A1, B2); fma2(acc[1][3], A1, B3);
    }

    float4 bias;
    bias.x = __ldcs(&Bv[(size_t)lo * OUTD + tj * 4 + 0]);
    bias.y = __ldcs(&Bv[(size_t)lo * OUTD + tj * 4 + 1]);
    bias.z = __ldcs(&Bv[(size_t)lo * OUTD + tj * 4 + 2]);
    bias.w = __ldcs(&Bv[(size_t)lo * OUTD + tj * 4 + 3]);
    float* Vout = g_V + (size_t)lo * NB * OUTD;
    #pragma unroll
    for (int p = 0; p < 2; p++) {
        float2 vx = upk(acc[p][0]), vy = upk(acc[p][1]),
               vz = upk(acc[p][2]), vw = upk(acc[p][3]);
        int n0 = tn * 4 + 2 * p;
        float4 o0 = make_float4(vx.x + bias.x, vy.x + bias.y, vz.x + bias.z, vw.x + bias.w);
        float4 o1 = make_float4(vx.y + bias.x, vy.y + bias.y, vz.y + bias.z, vw.y + bias.w);
        reinterpret_cast<float4*>(Vout + (size_t)n0 * OUTD)[tj]       = o0;
        reinterpret_cast<float4*>(Vout + (size_t)(n0 + 1) * OUTD)[tj] = o1;
    }
}

// ---------------- kernel 3a: E-step 0 (uniform R, streaming) -------------------
// grid = NB*NCH (bid: n = bid>>4, c = bid&15), block = 256.
// Warp w = o-quad {4w..4w+3}; lane = j-pair. Pure coalesced streaming of V.
__global__ __launch_bounds__(256) void em0_kernel(const float* __restrict__ bu)
{
    const int bid = blockIdx.x;
    const int n = bid >> 4, c = bid & (NCH - 1);
    const int tid = threadIdx.x;
    const int w = tid >> 5, lane = tid & 31;

    const float2* V2 = reinterpret_cast<const float2*>(g_V);

    float2 s1[4] = {}, s2[4] = {};
    #pragma unroll
    for (int li = 0; li < LCH; li++) {
        const int ll = c * LCH + li;
        float D = g_fa[ll * NB + n] * (1.f / 32.f);
        #pragma unroll
        for (int oq = 0; oq < 4; oq++) {
            int o = w * 4 + oq;
            float2 v = V2[(((size_t)ll * NO + o) * NB + n) * 32 + lane];
            float2 dv = make_float2(D * v.x, D * v.y);
            s1[oq].x += dv.x;               s1[oq].y += dv.y;
            s2[oq].x = fmaf(dv.x, v.x, s2[oq].x);
            s2[oq].y = fmaf(dv.y, v.y, s2[oq].y);
        }
    }
    #pragma unroll
    for (int oq = 0; oq < 4; oq++) {
        int o = w * 4 + oq;
        float2* q1 = reinterpret_cast<float2*>(g_q1 + ((size_t)bid * NO + o) * OUTD);
        float2* q2 = reinterpret_cast<float2*>(g_q2 + ((size_t)bid * NO + o) * OUTD);
        q1[lane] = s1[oq];
        q2[lane] = s2[oq];
    }

    if (w == 0) {
        float s0 = 0.f, sbu = 0.f, sfa = 0.f;
        #pragma unroll
        for (int li = 0; li < LCH; li++) {
            int ll = c * LCH + li;
            float fa = g_fa[ll * NB + n];
            s0 += fa * (1.f / 32.f);
            sbu = fmaf(bu[ll], fa * (1.f / 32.f), sbu);
            sfa += fa;
        }
        g_q0[bid * NO + lane]  = s0;    // same value per o (uniform R)
        g_qbu[bid * NO + lane] = sbu;
        if (lane == 0) g_qfa[bid] = sfa;
    }
}

// ---------------- kernel 3b: fused route + EM partials (lane = j-pair) --------
// grid = NB*NCH (bid: n = bid>>4, c = bid&15), block = 256 (8 warps).
// Phase 1: warp w -> l = c*8 + w; per o: coalesced row read + 5-shfl reduce;
//          butterfly leaves each lane holding logit(o = lane); warp softmax.
// Phase 2: warp w = o-quad; lane = j-pair; rows re-read (L1/L2-hot).
__global__ __launch_bounds__(256) void re_kernel(const float* __restrict__ bu)
{
    __shared__ float s_mu[NO * OUTD];   // (o, j) flat copy of g_mut[n]
    __shared__ float s_iv[NO * OUTD];
    __shared__ float s_C[NO];
    __shared__ float s_D[LCH][NO];

    const int bid = blockIdx.x;
    const int n = bid >> 4, c = bid & (NCH - 1);
    const int tid = threadIdx.x;
    const int w = tid >> 5, lane = tid & 31;

    {
        const float4* ms = reinterpret_cast<const float4*>(g_mut + (size_t)n * NO * OUTD);
        const float4* is = reinterpret_cast<const float4*>(g_ivt + (size_t)n * NO * OUTD);
        float4* md = reinterpret_cast<float4*>(s_mu);
        float4* id = reinterpret_cast<float4*>(s_iv);
        md[tid] = ms[tid]; md[tid + 256] = ms[tid + 256];
        id[tid] = is[tid]; id[tid + 256] = is[tid + 256];
        if (tid < NO) s_C[tid] = g_C[n * NO + tid];
        __syncthreads();
    }

    const float2* V2 = reinterpret_cast<const float2*>(g_V);
    const float2* mu2 = reinterpret_cast<const float2*>(s_mu);
    const float2* iv2 = reinterpret_cast<const float2*>(s_iv);

    // phase 1
    const int l = c * LCH + w;
    const float fa = g_fa[l * NB + n];
    float mylogit = 0.f;
    #pragma unroll 4
    for (int o = 0; o < NO; o++) {
        float2 v  = V2[(((size_t)l * NO + o) * NB + n) * 32 + lane];
        float2 mu = mu2[o * 32 + lane];
        float2 iv = iv2[o * 32 + lane];
        float d0 = v.x - mu.x, d1 = v.y - mu.y;
        float t = d0 * d0 * iv.x + d1 * d1 * iv.y;
        #pragma unroll
        for (int off = 16; off; off >>= 1) t += __shfl_xor_sync(0xffffffffu, t, off);
        if (lane == o) mylogit = s_C[o] - t;
    }
    // softmax over o (= lane)
    float mx = mylogit;
    #pragma unroll
    for (int off = 16; off; off >>= 1) mx = fmaxf(mx, __shfl_xor_sync(0xffffffffu, mx, off));
    float e = expf(mylogit - mx);
    float ss = e;
    #pragma unroll
    for (int off = 16; off; off >>= 1) ss += __shfl_xor_sync(0xffffffffu, ss, off);
    s_D[w][lane] = fa * (e / ss);
    __syncthreads();

    // phase 2: warp w = o-quad {4w..4w+3}; lane = j-pair
    float2 s1[4] = {}, s2[4] = {};
    #pragma unroll
    for (int li = 0; li < LCH; li++) {
        const int ll = c * LCH + li;
        #pragma unroll
        for (int oq = 0; oq < 4; oq++) {
            int o = w * 4 + oq;
            float D = s_D[li][o];
            float2 v = V2[(((size_t)ll * NO + o) * NB + n) * 32 + lane];
            float2 dv = make_float2(D * v.x, D * v.y);
            s1[oq].x += dv.x;               s1[oq].y += dv.y;
            s2[oq].x = fmaf(dv.x, v.x, s2[oq].x);
            s2[oq].y = fmaf(dv.y, v.y, s2[oq].y);
        }
    }
    #pragma unroll
    for (int oq = 0; oq < 4; oq++) {
        int o = w * 4 + oq;
        float2* q1 = reinterpret_cast<float2*>(g_q1 + ((size_t)bid * NO + o) * OUTD);
        float2* q2 = reinterpret_cast<float2*>(g_q2 + ((size_t)bid * NO + o) * OUTD);
        q1[lane] = s1[oq];
        q2[lane] = s2[oq];
    }

    if (w == 0) {
        float s0 = 0.f, sbu = 0.f, sfa = 0.f;
        #pragma unroll
        for (int li = 0; li < LCH; li++) {
            int ll = c * LCH + li;
            float Dl = s_D[li][lane];
            s0 += Dl;
            sbu = fmaf(bu[ll], Dl, sbu);
            sfa += g_fa[ll * NB + n];
        }
        g_q0[bid * NO + lane]  = s0;
        g_qbu[bid * NO + lane] = sbu;
        if (lane == 0) g_qfa[bid] = sfa;
    }
}

// ---------------- kernel 4: finalize EM ---------------------------------------
// grid = NB*4 (bid: n = bid>>2, og = bid&3), block = 512.
// Thread: o = og*8 + (tid>>6), j = tid&63. Full j-range per o -> computes C too.
__global__ __launch_bounds__(512) void fin_kernel(
    const float* __restrict__ bi, int write_out, float* __restrict__ out)
{
    const int bid = blockIdx.x;
    const int n = bid >> 2, og = bid & 3;
    const int tid = threadIdx.x;
    const int o = og * 8 + (tid >> 6);
    const int j = tid & 63;

    float s0 = 0.f, sbu = 0.f, sfa = 0.f;
    #pragma unroll
    for (int c = 0; c < NCH; c++) {
        s0  += g_q0[(n * NCH + c) * NO + o];
        sbu += g_qbu[(n * NCH + c) * NO + o];
        sfa += g_qfa[n * NCH + c];
    }
    float denom = s0 + EPSV;
    float a = sbu - bi[o] * (sfa - s0);

    float s1 = 0.f, s2 = 0.f;
    #pragma unroll
    for (int c = 0; c < NCH; c++) {
        size_t p = (((size_t)(n * NCH + c)) * NO + o) * OUTD + j;
        s1 += g_q1[p];
        s2 += g_q2[p];
    }
    float m   = s1 / denom;
    float var = fmaxf((s2 - 2.f * m * s1 + m * m * s0) / denom, 0.f);
    g_mut[((size_t)n * NO + o) * OUTD + j] = m;
    g_ivt[((size_t)n * NO + o) * OUTD + j] = 1.f / (2.f * var + EPSV);

    if (write_out) {
        out[NB * NO + ((size_t)n * NO + o) * OUTD + j] = m;    // mu_out (N, NO, OUT)
        if (j == 0) out[n * NO + o] = a;                       // a_out (N, NO)
    } else {
        // Sum log(var) over the 64 j for this o (2 warps), then C.
        float lv = logf(var + EPSV);
        #pragma unroll
        for (int off = 16; off; off >>= 1) lv += __shfl_xor_sync(0xffffffffu, lv, off);
        __shared__ float red[16];        // 16 warps
        __shared__ float s_a[8];
        const int wid = tid >> 5;
        if ((tid & 31) == 0) red[wid] = lv;
        if (j == 0) s_a[tid >> 6] = a;
        __syncthreads();
        if (tid < 8) {
            float slv = red[2 * tid] + red[2 * tid + 1];
            float av = s_a[tid];
            float lsig = (av > 0.f) ? -log1pf(expf(-av)) : av - log1pf(expf(av));
            g_C[n * NO + og * 8 + tid] =
                lsig - 1.f - 0.5f * 3.14159265358979323846f - 0.5f * slv;
        }
    }
}

// ---------------- launch --------------------------------------------------------
extern "C" void kernel_launch(void* const* d_in, const int* in_sizes, int n_in,
                              void* d_out, int out_size)
{
    const float* x      = (const float*)d_in[0];
    const float* Wscore = (const float*)d_in[1];
    const float* Bscore = (const float*)d_in[2];
    const float* Wcap   = (const float*)d_in[3];
    const float* Bcap   = (const float*)d_in[4];
    const float* Wvote  = (const float*)d_in[5];
    const float* Bvote  = (const float*)d_in[6];
    const float* bu     = (const float*)d_in[7];
    const float* bi     = (const float*)d_in[8];
    float* out = (float*)d_out;

    front_kernel<<<L * 2, 256>>>(x, Wscore, Bscore, Wcap, Bcap);
    vote_kernel<<<L * NO, 256>>>(Wvote, Bvote);

    // iters = 3: E0(uniform, streaming), route+E ×2
    em0_kernel<<<NB * NCH, 256>>>(bu);
    fin_kernel<<<NB * 4, 512>>>(bi, 0, out);
    re_kernel<<<NB * NCH, 256>>>(bu);
    fin_kernel<<<NB * 4, 512>>>(bi, 0, out);
    re_kernel<<<NB * NCH, 256>>>(bu);
    fin_kernel<<<NB * 4, 512>>>(bi, 1, out);
}

// round 12
// speedup vs baseline: 1.0722x; 1.0352x over previous
#include <cuda_runtime.h>
#include <math.h>

#define L    128
#define NB   64
#define DD   768
#define IN   64
#define OUTD 64
#define NO   32
#define EPSV 1e-8f
#define NCH  16         // l-chunks
#define LCH  8          // l per chunk

// ---------------- scratch (device globals) -----------------------------------
__device__ float g_mu_in[L * NB * IN];                 // (l, n, i)
__device__ float g_fa[L * NB];                         // (l, n)
__device__ float g_V [(size_t)L * NO * NB * OUTD];     // (l, o, n, j)  64 MB
__device__ float g_Vt[(size_t)NB * L * OUTD * NO];     // (n, l, j, o)  64 MB
__device__ float g_mut[NB * OUTD * NO];                // (n, j, o)
__device__ float g_ivt[NB * OUTD * NO];                // (n, j, o) : 1/(2var+eps)
__device__ float g_a[NB * NO];                         // (n, o) activation logit
__device__ float g_lvp[NB * 4 * NO];                   // (n, jg, o) partial sum log var
__device__ float g_q1[NB * NCH * OUTD * NO];           // chunk partials 8 MB
__device__ float g_q2[NB * NCH * OUTD * NO];           // 8 MB
__device__ float g_q0[NB * NCH * NO];
__device__ float g_qbu[NB * NCH * NO];
__device__ float g_qfa[NB * NCH];

// ---------------- packed f32x2 helpers ---------------------------------------
__device__ __forceinline__ unsigned long long pk(float x, float y) {
    unsigned long long r; asm("mov.b64 %0, {%1, %2};" : "=l"(r) : "f"(x), "f"(y)); return r;
}
__device__ __forceinline__ void fma2(unsigned long long& d, unsigned long long a, unsigned long long b) {
    asm("fma.rn.f32x2 %0, %1, %2, %0;" : "+l"(d) : "l"(a), "l"(b));
}
__device__ __forceinline__ float2 upk(unsigned long long v) {
    float2 r; asm("mov.b64 {%0, %1}, %2;" : "=f"(r.x), "=f"(r.y) : "l"(v)); return r;
}

// ---------------- kernel 1: a_in + mu_in (j-pair packing, clean smem) ---------
// grid = L*2 (l = bid>>1, n-half = bid&1), block = 256.
// acc packs i-pairs; A natural layout (conflict-free staging + broadcast reads).
__global__ __launch_bounds__(256) void front_kernel(
    const float* __restrict__ x,      // (N, L, D)
    const float* __restrict__ Wsc,    // (L, D)
    const float* __restrict__ Bsc,    // (L)
    const float* __restrict__ Wc,     // (L, D, IN)
    const float* __restrict__ Bc)     // (L, IN)
{
    __shared__ float As[32][33];                   // [n-half][k] natural
    __shared__ __align__(16) float Bs[32][64];     // [k][i]
    __shared__ float s_ws[32];
    __shared__ float s_sc[8][32];

    const int bid = blockIdx.x;
    const int l   = bid >> 1;
    const int n0  = (bid & 1) * 32;
    const int tid = threadIdx.x;
    const int tn  = tid >> 4;   // 0..15 -> n pair (2tn, 2tn+1)
    const int tj  = tid & 15;   // 0..15 -> i quad

    const int sq = tid >> 5, sn = tid & 31;
    float sc = 0.f;

    unsigned long long acc[2][2] = {};

    for (int kk = 0; kk < DD; kk += 32) {
        #pragma unroll
        for (int p = 0; p < 4; p++) {
            int e = tid + p * 256;
            int n = e >> 5, k = e & 31;
            As[n][k] = __ldcs(&x[((size_t)(n0 + n) * L + l) * DD + kk + k]);
        }
        #pragma unroll
        for (int p = 0; p < 8; p++) {
            int e = tid + p * 256;
            int k = e >> 6, i = e & 63;
            Bs[k][i] = __ldcs(&Wc[(size_t)l * DD * IN + (size_t)(kk + k) * IN + i]);
        }
        if (tid < 32) s_ws[tid] = Wsc[(size_t)l * DD + kk + tid];
        __syncthreads();

        #pragma unroll
        for (int k = 0; k < 32; k++) {
            float a0 = As[tn * 2 + 0][k];
            float a1 = As[tn * 2 + 1][k];
            unsigned long long A0 = pk(a0, a0), A1 = pk(a1, a1);
            ulonglong2 bb = reinterpret_cast<const ulonglong2*>(&Bs[k][0])[tj];
            fma2(acc[0][0], A0, bb.x); fma2(acc[0][1], A0, bb.y);
            fma2(acc[1][0], A1, bb.x); fma2(acc[1][1], A1, bb.y);
        }

        #pragma unroll
        for (int k4 = 0; k4 < 4; k4++)
            sc = fmaf(As[sn][sq * 4 + k4], s_ws[sq * 4 + k4], sc);
        __syncthreads();
    }

    // epilogue: bias + exact gelu; acc[r][c] = i-pair (tj*4+2c, +1) for n-local 2tn+r
    #pragma unroll
    for (int r = 0; r < 2; r++) {
        int n = n0 + tn * 2 + r;
        #pragma unroll
        for (int c = 0; c < 2; c++) {
            int i0 = tj * 4 + 2 * c;
            float2 v2 = upk(acc[r][c]);
            float v0 = v2.x + Bc[l * IN + i0];
            float v1 = v2.y + Bc[l * IN + i0 + 1];
            g_mu_in[(size_t)l * NB * IN + (size_t)n * IN + i0]     = v0 * normcdff(v0);
            g_mu_in[(size_t)l * NB * IN + (size_t)n * IN + i0 + 1] = v1 * normcdff(v1);
        }
    }

    s_sc[sq][sn] = sc;
    __syncthreads();
    if (tid < 32) {
        float s = Bsc[l];
        #pragma unroll
        for (int q = 0; q < 8; q++) s += s_sc[q][tid];
        g_fa[l * NB + n0 + tid] = 1.f / (1.f + expf(-s));
    }
}

// ---------------- kernel 2: votes V (j-pair packing, clean smem) ---------------
// grid = L*NO, block = 256. acc packs j-pairs; A natural [n][i] layout.
__global__ __launch_bounds__(256) void vote_kernel(
    const float* __restrict__ Wv,    // (L, NO, IN, OUT)
    const float* __restrict__ Bv)    // (L, NO, OUT)
{
    __shared__ float As[64][65];                   // [n][i] natural, conflict-free
    __shared__ __align__(16) float Bs[64][64];     // [i][j]

    const int lo  = blockIdx.x;   // l*32 + o
    const int l   = lo >> 5;
    const int tid = threadIdx.x;

    const float* A = g_mu_in + (size_t)l * NB * IN;
    const float* B = Wv + (size_t)lo * IN * OUTD;

    #pragma unroll
    for (int p = 0; p < 16; p++) {
        int e = tid + p * 256;
        As[e >> 6][e & 63] = A[e];              // consecutive -> conflict-free
        Bs[e >> 6][e & 63] = __ldcs(&B[e]);
    }
    __syncthreads();

    const int tn = tid >> 4, tj = tid & 15;
    unsigned long long acc[4][2];
    #pragma unroll
    for (int r = 0; r < 4; r++) { acc[r][0] = 0ULL; acc[r][1] = 0ULL; }

    #pragma unroll
    for (int i = 0; i < 64; i++) {
        float a0 = As[tn * 4 + 0][i];
        float a1 = As[tn * 4 + 1][i];
        float a2 = As[tn * 4 + 2][i];
        float a3 = As[tn * 4 + 3][i];
        unsigned long long A0 = pk(a0, a0), A1 = pk(a1, a1),
                           A2 = pk(a2, a2), A3 = pk(a3, a3);
        ulonglong2 bb = reinterpret_cast<const ulonglong2*>(&Bs[i][0])[tj];
        fma2(acc[0][0], A0, bb.x); fma2(acc[0][1], A0, bb.y);
        fma2(acc[1][0], A1, bb.x); fma2(acc[1][1], A1, bb.y);
        fma2(acc[2][0], A2, bb.x); fma2(acc[2][1], A2, bb.y);
        fma2(acc[3][0], A3, bb.x); fma2(acc[3][1], A3, bb.y);
    }

    float4 bias;
    bias.x = __ldcs(&Bv[(size_t)lo * OUTD + tj * 4 + 0]);
    bias.y = __ldcs(&Bv[(size_t)lo * OUTD + tj * 4 + 1]);
    bias.z = __ldcs(&Bv[(size_t)lo * OUTD + tj * 4 + 2]);
    bias.w = __ldcs(&Bv[(size_t)lo * OUTD + tj * 4 + 3]);
    float* Vout = g_V + (size_t)lo * NB * OUTD;
    #pragma unroll
    for (int r = 0; r < 4; r++) {
        float2 p0 = upk(acc[r][0]);    // j = tj*4, tj*4+1
        float2 p1 = upk(acc[r][1]);    // j = tj*4+2, tj*4+3
        float4 o4 = make_float4(p0.x + bias.x, p0.y + bias.y,
                                p1.x + bias.z, p1.y + bias.w);
        reinterpret_cast<float4*>(Vout + (size_t)(tn * 4 + r) * OUTD)[tj] = o4;
    }
}

// ---------------- kernel 2b: fused transpose + uniform E-step -----------------
// grid = NB*NCH (bid: n = bid>>4, c = bid&15), block = 256.
__global__ __launch_bounds__(256) void trE0_kernel(const float* __restrict__ bu)
{
    __shared__ float sm[NO * 65];
    const int bid = blockIdx.x;
    const int n = bid >> 4, c = bid & (NCH - 1);
    const int tid = threadIdx.x;
    const int o = tid & 31, jw = tid >> 5;

    float s1[8] = {}, s2[8] = {};
    float s0 = 0.f, sbu = 0.f, sfa = 0.f;

    for (int li = 0; li < LCH; li++) {
        const int l = c * LCH + li;
        #pragma unroll
        for (int r = 0; r < 2; r++) {
            int idx = tid + r * 256;       // 0..511
            int oo = idx >> 4, f4 = idx & 15;
            float4 v = __ldcs(reinterpret_cast<const float4*>(
                g_V + (((size_t)l * NO + oo) * NB + n) * OUTD) + f4);
            float* d = sm + oo * 65 + f4 * 4;
            d[0] = v.x; d[1] = v.y; d[2] = v.z; d[3] = v.w;
        }
        __syncthreads();

        float fa = g_fa[l * NB + n];
        float D = fa * (1.f / 32.f);
        float* vt = g_Vt + ((size_t)n * L + l) * OUTD * NO;
        #pragma unroll
        for (int k = 0; k < 8; k++) {
            int j = jw * 8 + k;
            float v = sm[o * 65 + j];
            vt[j * NO + o] = v;
            float dv = D * v;
            s1[k] += dv;
            s2[k] = fmaf(dv, v, s2[k]);
        }
        s0 += D; sbu = fmaf(bu[l], D, sbu); sfa += fa;
        __syncthreads();
    }

    const int j0 = jw * 8;
    float* q1 = g_q1 + ((size_t)bid * OUTD + j0) * NO + o;
    float* q2 = g_q2 + ((size_t)bid * OUTD + j0) * NO + o;
    #pragma unroll
    for (int k = 0; k < 8; k++) { q1[k * NO] = s1[k]; q2[k * NO] = s2[k]; }
    if (jw == 0) {
        g_q0[bid * NO + o]  = s0;
        g_qbu[bid * NO + o] = sbu;
        if (o == 0) g_qfa[bid] = sfa;
    }
}

// ---------------- kernel 3: fused route + EM partials (lane = o) --------------
// grid = NB*NCH (bid: n = bid>>4, c = bid&15), block = 256 (8 warps, 1 l each).
__global__ __launch_bounds__(256) void re_kernel(const float* __restrict__ bu)
{
    __shared__ float s_mu[OUTD * NO];   // (j, o)
    __shared__ float s_iv[OUTD * NO];
    __shared__ float s_C[NO];
    __shared__ float s_D[LCH][NO];

    const int bid = blockIdx.x;
    const int n = bid >> 4, c = bid & (NCH - 1);
    const int tid = threadIdx.x;
    const int w = tid >> 5, lane = tid & 31;

    {
        const float4* ms = reinterpret_cast<const float4*>(g_mut + (size_t)n * OUTD * NO);
        const float4* is = reinterpret_cast<const float4*>(g_ivt + (size_t)n * OUTD * NO);
        float4* md = reinterpret_cast<float4*>(s_mu);
        float4* id = reinterpret_cast<float4*>(s_iv);
        md[tid] = ms[tid]; md[tid + 256] = ms[tid + 256];
        id[tid] = is[tid]; id[tid + 256] = is[tid + 256];
        if (tid < NO) {
            float a = g_a[n * NO + tid];
            float slv = g_lvp[(n * 4 + 0) * NO + tid] + g_lvp[(n * 4 + 1) * NO + tid]
                      + g_lvp[(n * 4 + 2) * NO + tid] + g_lvp[(n * 4 + 3) * NO + tid];
            float lsig = (a > 0.f) ? -log1pf(expf(-a)) : a - log1pf(expf(a));
            s_C[tid] = lsig - 1.f - 0.5f * 3.14159265358979323846f - 0.5f * slv;
        }
        __syncthreads();
    }

    // phase 1: warp w -> l = c*8 + w; lane = o; zero barriers
    const int l = c * LCH + w;
    const float fa = g_fa[l * NB + n];
    float D;
    {
        const float* vb = g_Vt + ((size_t)n * L + l) * OUTD * NO + lane;
        float t = 0.f;
        #pragma unroll
        for (int j = 0; j < OUTD; j++) {
            float v = vb[j * NO];
            float d = v - s_mu[j * NO + lane];
            t = fmaf(d * d, s_iv[j * NO + lane], t);
        }
        float lg = s_C[lane] - t;
        float mx = lg;
        #pragma unroll
        for (int off = 16; off; off >>= 1) mx = fmaxf(mx, __shfl_xor_sync(0xffffffffu, mx, off));
        float e = expf(lg - mx);
        float ss = e;
        #pragma unroll
        for (int off = 16; off; off >>= 1) ss += __shfl_xor_sync(0xffffffffu, ss, off);
        D = fa * (e / ss);
    }
    s_D[w][lane] = D;
    __syncthreads();

    // phase 2: warp w owns j-slice [w*8, w*8+8); lane = o; accumulate over 8 l
    float s1[8] = {}, s2[8] = {};
    const int j0 = w * 8;
    #pragma unroll
    for (int li = 0; li < LCH; li++) {
        float Dl = s_D[li][lane];
        const float* vb = g_Vt + (((size_t)n * L + c * LCH + li) * OUTD + j0) * NO + lane;
        #pragma unroll
        for (int jj = 0; jj < 8; jj++) {
            float v = vb[jj * NO];
            float dv = Dl * v;
            s1[jj] += dv;
            s2[jj] = fmaf(dv, v, s2[jj]);
        }
    }
    float* q1 = g_q1 + ((size_t)bid * OUTD + j0) * NO + lane;
    float* q2 = g_q2 + ((size_t)bid * OUTD + j0) * NO + lane;
    #pragma unroll
    for (int jj = 0; jj < 8; jj++) { q1[jj * NO] = s1[jj]; q2[jj * NO] = s2[jj]; }

    if (w == 0) {
        float s0 = 0.f, sbu = 0.f, sfa = 0.f;
        #pragma unroll
        for (int li = 0; li < LCH; li++) {
            int ll = c * LCH + li;
            float Dl = s_D[li][lane];
            s0 += Dl;
            sbu = fmaf(bu[ll], Dl, sbu);
            sfa += g_fa[ll * NB + n];
        }
        g_q0[bid * NO + lane]  = s0;
        g_qbu[bid * NO + lane] = sbu;
        if (lane == 0) g_qfa[bid] = sfa;
    }
}

// ---------------- kernel 4: finalize EM (parallel, one (j,o) per thread) ------
// grid = NB*4 (bid: n = bid>>2, jg = bid&3), block = 512.
__global__ __launch_bounds__(512) void fin_kernel(
    const float* __restrict__ bi, int write_out, float* __restrict__ out)
{
    const int bid = blockIdx.x;
    const int n = bid >> 2, jg = bid & 3;
    const int tid = threadIdx.x;
    const int jj = tid >> 5, o = tid & 31;
    const int j = jg * 16 + jj;

    float s0 = 0.f, sbu = 0.f, sfa = 0.f;
    #pragma unroll
    for (int c = 0; c < NCH; c++) {
        s0  += g_q0[(n * NCH + c) * NO + o];
        sbu += g_qbu[(n * NCH + c) * NO + o];
        sfa += g_qfa[n * NCH + c];
    }
    float denom = s0 + EPSV;
    float a = sbu - bi[o] * (sfa - s0);

    float s1 = 0.f, s2 = 0.f;
    #pragma unroll
    for (int c = 0; c < NCH; c++) {
        size_t p = (((size_t)(n * NCH + c)) * OUTD + j) * NO + o;
        s1 += g_q1[p];
        s2 += g_q2[p];
    }
    float m   = s1 / denom;
    float var = fmaxf((s2 - 2.f * m * s1 + m * m * s0) / denom, 0.f);
    g_mut[((size_t)n * OUTD + j) * NO + o] = m;
    g_ivt[((size_t)n * OUTD + j) * NO + o] = 1.f / (2.f * var + EPSV);

    if (write_out) {
        out[NB * NO + ((size_t)n * NO + o) * OUTD + j] = m;    // mu_out (N, NO, OUT)
        if (jj == 0 && jg == 0) out[n * NO + o] = a;           // a_out (N, NO)
    } else {
        float lv = logf(var + EPSV);
        __shared__ float s_lv[16][NO];
        s_lv[jj][o] = lv;
        __syncthreads();
        if (jj == 0) {
            float slv = 0.f;
            #pragma unroll
            for (int k = 0; k < 16; k++) slv += s_lv[k][o];
            g_lvp[(n * 4 + jg) * NO + o] = slv;
            if (jg == 0) g_a[n * NO + o] = a;
        }
    }
}

// ---------------- launch --------------------------------------------------------
extern "C" void kernel_launch(void* const* d_in, const int* in_sizes, int n_in,
                              void* d_out, int out_size)
{
    const float* x      = (const float*)d_in[0];
    const float* Wscore = (const float*)d_in[1];
    const float* Bscore = (const float*)d_in[2];
    const float* Wcap   = (const float*)d_in[3];
    const float* Bcap   = (const float*)d_in[4];
    const float* Wvote  = (const float*)d_in[5];
    const float* Bvote  = (const float*)d_in[6];
    const float* bu     = (const float*)d_in[7];
    const float* bi     = (const float*)d_in[8];
    float* out = (float*)d_out;

    front_kernel<<<L * 2, 256>>>(x, Wscore, Bscore, Wcap, Bcap);
    vote_kernel<<<L * NO, 256>>>(Wvote, Bvote);

    // iters = 3: E0 fused with transpose, then route+E ×2
    trE0_kernel<<<NB * NCH, 256>>>(bu);
    fin_kernel<<<NB * 4, 512>>>(bi, 0, out);
    re_kernel<<<NB * NCH, 256>>>(bu);
    fin_kernel<<<NB * 4, 512>>>(bi, 0, out);
    re_kernel<<<NB * NCH, 256>>>(bu);
    fin_kernel<<<NB * 4, 512>>>(bi, 1, out);
}